// round 3
// baseline (speedup 1.0000x reference)
#include <cuda_runtime.h>
#include <float.h>

#define HW 4096
#define NB 4

// ---------------- scratch (device globals: no allocations allowed) ----------
__device__ float g_qT[NB * HW * 8];        // [b][s][d]  512 KB
__device__ float g_kT[NB * HW * 8];        // [b][t][d]  512 KB
__device__ float g_xT[NB * HW * 64];       // [b][s][c]  4 MB
__device__ int   g_idx[NB * HW * 9];       // [b][t][9]  576 KB
__device__ float g_Wt[576 * 64];           // [kk*64+c][o] 147 KB

// ---------------- prep: weight transpose (OC,C,9) -> Wt[kk*64+c][o] ---------
__global__ void k_prep_w(const float* __restrict__ W) {
    int j = blockIdx.x * 256 + threadIdx.x;
    if (j >= 576 * 64) return;
    int r = j >> 6, o = j & 63;
    int kk = r >> 6, c = r & 63;
    g_Wt[j] = W[o * 576 + c * 9 + kk];
}

// ---------------- k1: 1x1 convs (q,k) + x transpose -------------------------
__global__ void k_proj(const float* __restrict__ x, const float* __restrict__ qw,
                       const float* __restrict__ qb, const float* __restrict__ kw,
                       const float* __restrict__ kb) {
    __shared__ float tile[64][129];
    __shared__ float wq[512], wk[512];
    int tid = threadIdx.x;
    int b  = blockIdx.x >> 5;
    int s0 = (blockIdx.x & 31) << 7;

    for (int u = tid; u < 512; u += 128) { wq[u] = qw[u]; wk[u] = kw[u]; }
    for (int u = tid; u < 64 * 128; u += 128) {
        int c = u >> 7, sl = u & 127;
        tile[c][sl] = x[(b * 64 + c) * HW + s0 + sl];
    }
    __syncthreads();

    for (int u = tid; u < 128 * 64; u += 128) {
        int sl = u >> 6, c = u & 63;
        g_xT[((size_t)b * HW + s0 + sl) * 64 + c] = tile[c][sl];
    }

    float qa[8], ka[8];
    #pragma unroll
    for (int d = 0; d < 8; ++d) { qa[d] = __ldg(qb + d); ka[d] = __ldg(kb + d); }
    int sl = tid;
    #pragma unroll 4
    for (int c = 0; c < 64; ++c) {
        float xv = tile[c][sl];
        #pragma unroll
        for (int d = 0; d < 8; ++d) {
            qa[d] = fmaf(wq[d * 64 + c], xv, qa[d]);
            ka[d] = fmaf(wk[d * 64 + c], xv, ka[d]);
        }
    }
    float4* qT4 = (float4*)g_qT;
    float4* kT4 = (float4*)g_kT;
    int base = (b * HW + s0 + sl) * 2;
    qT4[base]     = make_float4(qa[0], qa[1], qa[2], qa[3]);
    qT4[base + 1] = make_float4(qa[4], qa[5], qa[6], qa[7]);
    kT4[base]     = make_float4(ka[0], ka[1], ka[2], ka[3]);
    kT4[base + 1] = make_float4(ka[4], ka[5], ka[6], ka[7]);
}

// ---------------- k2: fused energy + top-9 ----------------------------------
// grid 512 (4 b x 128 tblocks), block 128. 32 t per block, 4 s-partitions.
// Streaming top-9 kept UNSORTED with a running min: insert = replace-min
// (~35 instr) instead of sorted insert (~54). Sorted once at the end.
__global__ void __launch_bounds__(128) k_topk() {
    __shared__ float4 qs4[1024];              // 512 s x 8 floats (16 KB)
    __shared__ float  mval[32 * 4 * 9];
    __shared__ int    midx[32 * 4 * 9];
    int tid  = threadIdx.x;
    int h    = tid >> 5;                      // 0..3 : s-partition (warp id)
    int tl   = tid & 31;                      // 0..31: local t
    int b    = blockIdx.x >> 7;
    int t0   = (blockIdx.x & 127) << 5;
    int t    = t0 + tl;

    const float4* kT4 = (const float4*)g_kT;
    float4 kA = kT4[(b * HW + t) * 2];
    float4 kB = kT4[(b * HW + t) * 2 + 1];

    float v[9]; int ix[9];
    #pragma unroll
    for (int j = 0; j < 9; ++j) { v[j] = -FLT_MAX; ix[j] = -1; }
    float vmin = -FLT_MAX;

    const float4* qbase = ((const float4*)g_qT) + (size_t)b * HW * 2;
    for (int cb = 0; cb < HW; cb += 512) {
        __syncthreads();
        for (int u = tid; u < 1024; u += 128) qs4[u] = qbase[cb * 2 + u];
        __syncthreads();
        #pragma unroll 4
        for (int i = 0; i < 128; ++i) {
            int sl = (i << 2) | h;
            float4 A  = qs4[sl * 2];
            float4 Bq = qs4[sl * 2 + 1];
            float e  = kA.x * A.x;
            e  = fmaf(kA.y, A.y, e);
            e  = fmaf(kA.z, A.z, e);
            e  = fmaf(kA.w, A.w, e);
            float e2 = kB.x * Bq.x;
            e2 = fmaf(kB.y, Bq.y, e2);
            e2 = fmaf(kB.z, Bq.z, e2);
            e2 = fmaf(kB.w, Bq.w, e2);
            e += e2;
            if (e > vmin) {                   // rare: replace-min, recompute min
                bool done = false;
                #pragma unroll
                for (int j = 0; j < 9; ++j) {
                    bool m = (!done) && (v[j] == vmin);
                    if (m) { v[j] = e; ix[j] = cb + sl; done = true; }
                }
                float m0 = fminf(v[0], v[1]);
                float m1 = fminf(v[2], v[3]);
                float m2 = fminf(v[4], v[5]);
                float m3 = fminf(v[6], v[7]);
                m0 = fminf(m0, m1); m2 = fminf(m2, m3);
                vmin = fminf(fminf(m0, m2), v[8]);
            }
        }
    }

    // sort own 9: (val desc, idx asc)
    #pragma unroll
    for (int p = 0; p < 8; ++p)
        #pragma unroll
        for (int j = 0; j < 8 - p; ++j) {
            bool sw = (v[j] < v[j + 1]) || (v[j] == v[j + 1] && ix[j] > ix[j + 1]);
            if (sw) {
                float tv = v[j]; v[j] = v[j + 1]; v[j + 1] = tv;
                int   ti = ix[j]; ix[j] = ix[j + 1]; ix[j + 1] = ti;
            }
        }

    int mbase = (tl * 4 + h) * 9;
    #pragma unroll
    for (int j = 0; j < 9; ++j) { mval[mbase + j] = v[j]; midx[mbase + j] = ix[j]; }
    __syncthreads();

    if (h == 0) {
        float mv[9]; int mi[9];
        #pragma unroll
        for (int j = 0; j < 9; ++j) { mv[j] = v[j]; mi[j] = ix[j]; }
        for (int hh = 1; hh < 4; ++hh) {
            int cbs = (tl * 4 + hh) * 9;
            for (int j = 0; j < 9; ++j) {
                float cv = mval[cbs + j]; int ci = midx[cbs + j];
                if (cv > mv[8] || (cv == mv[8] && ci < mi[8])) {
                    mv[8] = cv; mi[8] = ci;
                    #pragma unroll
                    for (int j2 = 8; j2 > 0; --j2) {
                        bool sw = (mv[j2] > mv[j2 - 1]) ||
                                  (mv[j2] == mv[j2 - 1] && mi[j2] < mi[j2 - 1]);
                        if (sw) {
                            float tv = mv[j2]; mv[j2] = mv[j2 - 1]; mv[j2 - 1] = tv;
                            int   ti = mi[j2]; mi[j2] = mi[j2 - 1]; mi[j2 - 1] = ti;
                        }
                    }
                } else break;                 // cv sorted desc: rest can't qualify
            }
        }
        // sort indices ascending (reference sorts idx)
        #pragma unroll
        for (int p = 0; p < 8; ++p)
            #pragma unroll
            for (int j = 0; j < 8 - p; ++j)
                if (mi[j] > mi[j + 1]) {
                    int ti = mi[j]; mi[j] = mi[j + 1]; mi[j + 1] = ti;
                }
        #pragma unroll
        for (int j = 0; j < 9; ++j)
            g_idx[((size_t)b * HW + t) * 9 + j] = mi[j];
    }
}

// ---------------- k3: gather + 9-tap conv + relu + residual -----------------
// Register-tiled GEMM: tile = 128 t x 64 o per block, each thread 4t x 4o.
// W in smem (147 KB) + r-chunked gather buffer [128 t][132] (67.6 KB).
// Per r per warp: 1 LDS.128 (2 phases) + 4 broadcast LDS (4 phases) feeds
// 16 warp-FFMA (32 pipe-cyc) -> FFMA-pipe bound, not crossbar.
__global__ void __launch_bounds__(512, 1) k_conv(const float* __restrict__ bias,
                                                 const float* __restrict__ gamma,
                                                 float* __restrict__ out) {
    extern __shared__ float sm[];
    float* Wsm  = sm;                          // 36864 floats
    float* gbuf = sm + 36864;                  // [128 t][132]
    int*   idxs = (int*)(sm + 36864 + 128 * 132);  // 1152 ints
    int tid = threadIdx.x;
    int b  = blockIdx.x >> 5;
    int t0 = (blockIdx.x & 31) << 7;           // 128 t per tile

    for (int u = tid; u < 36864; u += 512) Wsm[u] = g_Wt[u];
    for (int u = tid; u < 1152; u += 512)
        idxs[u] = g_idx[((size_t)b * HW + t0) * 9 + u];

    int og = tid & 15;                         // 4 o each
    int tg = tid >> 4;                         // 0..31 -> 4 t each
    float4 acc0 = make_float4(0.f,0.f,0.f,0.f);
    float4 acc1 = make_float4(0.f,0.f,0.f,0.f);
    float4 acc2 = make_float4(0.f,0.f,0.f,0.f);
    float4 acc3 = make_float4(0.f,0.f,0.f,0.f);

    const float4* xT4 = ((const float4*)g_xT) + (size_t)b * HW * 16;
    const float4* W4  = (const float4*)Wsm;
    float4* g4 = (float4*)gbuf;
    const float* gp0 = gbuf + (tg * 4 + 0) * 132;
    const float* gp1 = gbuf + (tg * 4 + 1) * 132;
    const float* gp2 = gbuf + (tg * 4 + 2) * 132;
    const float* gp3 = gbuf + (tg * 4 + 3) * 132;
    __syncthreads();

    for (int chunk = 0; chunk < 5; ++chunk) {
        int kb  = chunk * 2;
        int nkk = (chunk < 4) ? 2 : 1;
        int sh  = (nkk == 2) ? 5 : 4;          // log2(nkk*16)
        // gather this r-chunk: gbuf[t][kk*64 + c] <- xT[pos][c], L2-only loads
        int tot = 128 << sh;                   // 128 t * nkk*16 float4
        for (int u = tid; u < tot; u += 512) {
            int tl = u >> sh;
            int vv = u & ((1 << sh) - 1);
            int kk = vv >> 4, c4 = vv & 15;
            int pos = idxs[tl * 9 + kb + kk];
            g4[tl * 33 + (kk << 4) + c4] = __ldcg(&xT4[pos * 16 + c4]);
        }
        __syncthreads();

        int nr = nkk << 6;
        int rg0 = kb << 6;                     // global r base
        #pragma unroll 4
        for (int rl = 0; rl < nr; ++rl) {
            float4 wv = W4[((rg0 + rl) << 4) + og];   // 2 phases
            float gA = gp0[rl];                        // broadcast
            float gB = gp1[rl];
            float gC = gp2[rl];
            float gD = gp3[rl];
            acc0.x = fmaf(wv.x, gA, acc0.x); acc0.y = fmaf(wv.y, gA, acc0.y);
            acc0.z = fmaf(wv.z, gA, acc0.z); acc0.w = fmaf(wv.w, gA, acc0.w);
            acc1.x = fmaf(wv.x, gB, acc1.x); acc1.y = fmaf(wv.y, gB, acc1.y);
            acc1.z = fmaf(wv.z, gB, acc1.z); acc1.w = fmaf(wv.w, gB, acc1.w);
            acc2.x = fmaf(wv.x, gC, acc2.x); acc2.y = fmaf(wv.y, gC, acc2.y);
            acc2.z = fmaf(wv.z, gC, acc2.z); acc2.w = fmaf(wv.w, gC, acc2.w);
            acc3.x = fmaf(wv.x, gD, acc3.x); acc3.y = fmaf(wv.y, gD, acc3.y);
            acc3.z = fmaf(wv.z, gD, acc3.z); acc3.w = fmaf(wv.w, gD, acc3.w);
        }
        __syncthreads();
    }

    // epilogue: bias + relu + gamma*out + residual
    float gamma0 = __ldg(gamma);
    float4 bv = __ldg(((const float4*)bias) + og);
    int o0 = og << 2;
    float4 accs[4] = {acc0, acc1, acc2, acc3};
    #pragma unroll
    for (int j = 0; j < 4; ++j) {
        int t = t0 + tg * 4 + j;
        float4 res = __ldcg(&((const float4*)g_xT)[((size_t)b * HW + t) * 16 + og]);
        float* outp = out + ((size_t)b * 64 + o0) * HW + t;
        outp[0]          = fmaf(gamma0, fmaxf(accs[j].x + bv.x, 0.f), res.x);
        outp[HW]         = fmaf(gamma0, fmaxf(accs[j].y + bv.y, 0.f), res.y);
        outp[2 * HW]     = fmaf(gamma0, fmaxf(accs[j].z + bv.z, 0.f), res.z);
        outp[3 * HW]     = fmaf(gamma0, fmaxf(accs[j].w + bv.w, 0.f), res.w);
    }
}

// ---------------- launch ----------------------------------------------------
extern "C" void kernel_launch(void* const* d_in, const int* in_sizes, int n_in,
                              void* d_out, int out_size) {
    const float* x      = (const float*)d_in[0];
    const float* qw     = (const float*)d_in[1];
    const float* qb     = (const float*)d_in[2];
    const float* kw     = (const float*)d_in[3];
    const float* kb     = (const float*)d_in[4];
    const float* gamma  = (const float*)d_in[5];
    const float* weight = (const float*)d_in[6];
    const float* bias   = (const float*)d_in[7];
    float* out = (float*)d_out;

    // W(147456) + gbuf(67584) + idx(4608) = 219648 B dynamic smem
    cudaFuncSetAttribute(k_conv, cudaFuncAttributeMaxDynamicSharedMemorySize, 219648);

    k_prep_w<<<144, 256>>>(weight);
    k_proj<<<128, 128>>>(x, qw, qb, kw, kb);
    k_topk<<<512, 128>>>();
    k_conv<<<128, 512, 219648>>>(bias, gamma, out);
}

// round 4
// speedup vs baseline: 1.4432x; 1.4432x over previous
#include <cuda_runtime.h>
#include <float.h>

#define HW 4096
#define NB 4
#define FULLW 0xffffffffu

// ---------------- scratch (device globals: no allocations allowed) ----------
__device__ float g_qT[NB * HW * 8];        // [b][s][d]  512 KB
__device__ float g_kT[NB * HW * 8];        // [b][t][d]  512 KB
__device__ float g_xT[NB * HW * 64];       // [b][s][c]  4 MB
__device__ int   g_idx[NB * HW * 9];       // [b][t][9]  576 KB
__device__ float g_Wt[576 * 64];           // [kk*64+c][o] 147 KB

// ---------------- prep: weight transpose (OC,C,9) -> Wt[kk*64+c][o] ---------
__global__ void k_prep_w(const float* __restrict__ W) {
    int j = blockIdx.x * 256 + threadIdx.x;
    if (j >= 576 * 64) return;
    int r = j >> 6, o = j & 63;
    int kk = r >> 6, c = r & 63;
    g_Wt[j] = W[o * 576 + c * 9 + kk];
}

// ---------------- k1: 1x1 convs (q,k) + x transpose -------------------------
__global__ void k_proj(const float* __restrict__ x, const float* __restrict__ qw,
                       const float* __restrict__ qb, const float* __restrict__ kw,
                       const float* __restrict__ kb) {
    __shared__ float tile[64][129];
    __shared__ float wq[512], wk[512];
    int tid = threadIdx.x;
    int b  = blockIdx.x >> 5;
    int s0 = (blockIdx.x & 31) << 7;

    for (int u = tid; u < 512; u += 128) { wq[u] = qw[u]; wk[u] = kw[u]; }
    for (int u = tid; u < 64 * 128; u += 128) {
        int c = u >> 7, sl = u & 127;
        tile[c][sl] = x[(b * 64 + c) * HW + s0 + sl];
    }
    __syncthreads();

    for (int u = tid; u < 128 * 64; u += 128) {
        int sl = u >> 6, c = u & 63;
        g_xT[((size_t)b * HW + s0 + sl) * 64 + c] = tile[c][sl];
    }

    float qa[8], ka[8];
    #pragma unroll
    for (int d = 0; d < 8; ++d) { qa[d] = __ldg(qb + d); ka[d] = __ldg(kb + d); }
    int sl = tid;
    #pragma unroll 4
    for (int c = 0; c < 64; ++c) {
        float xv = tile[c][sl];
        #pragma unroll
        for (int d = 0; d < 8; ++d) {
            qa[d] = fmaf(wq[d * 64 + c], xv, qa[d]);
            ka[d] = fmaf(wk[d * 64 + c], xv, ka[d]);
        }
    }
    float4* qT4 = (float4*)g_qT;
    float4* kT4 = (float4*)g_kT;
    int base = (b * HW + s0 + sl) * 2;
    qT4[base]     = make_float4(qa[0], qa[1], qa[2], qa[3]);
    qT4[base + 1] = make_float4(qa[4], qa[5], qa[6], qa[7]);
    kT4[base]     = make_float4(ka[0], ka[1], ka[2], ka[3]);
    kT4[base + 1] = make_float4(ka[4], ka[5], ka[6], ka[7]);
}

// ---------------- top-9 insert: warp-uniform, sorted desc, strict > ---------
__device__ __forceinline__ void ins9(float val, int s, float v[9], int ix[9]) {
    if (val > v[8]) {                   // strict: equal keeps earlier index
        v[8] = val; ix[8] = s;
        #pragma unroll
        for (int j = 8; j > 0; --j) {
            if (v[j] > v[j - 1]) {      // strict: stable for equals
                float tv = v[j]; v[j] = v[j - 1]; v[j - 1] = tv;
                int   ti = ix[j]; ix[j] = ix[j - 1]; ix[j - 1] = ti;
            }
        }
    }
}

// ---------------- k2: energy GEMM -> smem, warp-uniform ballot top-9 --------
// grid 1024 (4 b x 256 tiles of 16 t), block 512 (16 warps).
// Phase A: broadcast-q GEMM writes e to ebuf[16][516].
// Phase B: warp w scans row w with ballot vs theta=v[8]; inserts are uniform.
__global__ void __launch_bounds__(512, 2) k_topk2() {
    extern __shared__ float sm2[];
    float4* qs4 = (float4*)sm2;            // 1024 float4 (16 KB)
    float*  ebuf = sm2 + 4096;             // 16 * 516 floats (33 KB)
    int tid  = threadIdx.x;
    int w    = tid >> 5, lane = tid & 31;
    int b    = blockIdx.x >> 8;
    int t0   = (blockIdx.x & 255) << 4;
    int tg   = lane & 15;                  // GEMM: lane -> t
    int sg   = lane >> 4;                  // GEMM: 2 s per step

    const float4* kT4 = (const float4*)g_kT;
    float4 kA = kT4[(b * HW + t0 + tg) * 2];
    float4 kB = kT4[(b * HW + t0 + tg) * 2 + 1];

    float v[9]; int ix[9];
    #pragma unroll
    for (int j = 0; j < 9; ++j) { v[j] = -FLT_MAX; ix[j] = -1; }

    const float4* qbase = ((const float4*)g_qT) + (size_t)b * HW * 2;
    for (int chunk = 0; chunk < 8; ++chunk) {
        int s0 = chunk << 9;
        // stage q chunk (disjoint from ebuf: safe vs other warps' scan)
        qs4[tid]       = qbase[s0 * 2 + tid];
        qs4[tid + 512] = qbase[s0 * 2 + tid + 512];
        __syncthreads();                   // q ready AND all scans of prev chunk done

        // GEMM: warp w covers sl in [w*32, w*32+32), 2 s per step
        #pragma unroll 4
        for (int j = 0; j < 16; ++j) {
            int sl = (w << 5) + (j << 1) + sg;
            float4 A  = qs4[sl * 2];
            float4 Bq = qs4[sl * 2 + 1];
            float e  = kA.x * A.x;
            e  = fmaf(kA.y, A.y, e);
            e  = fmaf(kA.z, A.z, e);
            e  = fmaf(kA.w, A.w, e);
            float e2 = kB.x * Bq.x;
            e2 = fmaf(kB.y, Bq.y, e2);
            e2 = fmaf(kB.z, Bq.z, e2);
            e2 = fmaf(kB.w, Bq.w, e2);
            ebuf[tg * 516 + sl] = e + e2;
        }
        __syncthreads();                   // ebuf ready

        // scan: warp w owns row w (one t, warp-shared threshold)
        const float* row = ebuf + w * 516;
        #pragma unroll
        for (int g = 0; g < 4; ++g) {
            float4 ev = *(const float4*)(row + (g << 7) + (lane << 2));
            float m = fmaxf(fmaxf(ev.x, ev.y), fmaxf(ev.z, ev.w));
            unsigned bal = __ballot_sync(FULLW, m > v[8]);
            int sb0 = s0 + (g << 7);
            while (bal) {                  // warp-uniform loop
                int src = __ffs(bal) - 1; bal &= bal - 1;
                float c0 = __shfl_sync(FULLW, ev.x, src);
                float c1 = __shfl_sync(FULLW, ev.y, src);
                float c2 = __shfl_sync(FULLW, ev.z, src);
                float c3 = __shfl_sync(FULLW, ev.w, src);
                int sb = sb0 + (src << 2);
                ins9(c0, sb,     v, ix);
                ins9(c1, sb + 1, v, ix);
                ins9(c2, sb + 2, v, ix);
                ins9(c3, sb + 3, v, ix);
            }
        }
    }

    // sort indices ascending (reference sorts idx); uniform across warp
    #pragma unroll
    for (int p = 0; p < 8; ++p)
        #pragma unroll
        for (int j = 0; j < 8 - p; ++j)
            if (ix[j] > ix[j + 1]) {
                int ti = ix[j]; ix[j] = ix[j + 1]; ix[j + 1] = ti;
            }
    if (lane == 0) {
        #pragma unroll
        for (int j = 0; j < 9; ++j)
            g_idx[((size_t)b * HW + t0 + w) * 9 + j] = ix[j];
    }
}

// ---------------- k3: gather + 9-tap conv + relu + residual -----------------
// Register-tiled: 128 t x 64 o per block, thread = 4t x 4o. 9 chunks of 64 r
// with register-prefetched gather (LDG of chunk kk+1 hidden under compute kk).
__global__ void __launch_bounds__(512, 1) k_conv(const float* __restrict__ bias,
                                                 const float* __restrict__ gamma,
                                                 float* __restrict__ out) {
    extern __shared__ float sm[];
    float* Wsm  = sm;                          // 36864 floats
    float* gbuf = sm + 36864;                  // 128 rows x 68 floats (17 float4)
    int*   idxs = (int*)(sm + 36864 + 128 * 68);   // 1152 ints
    int tid = threadIdx.x;
    int b  = blockIdx.x >> 5;
    int t0 = (blockIdx.x & 31) << 7;

    for (int u = tid; u < 36864; u += 512) Wsm[u] = g_Wt[u];
    for (int u = tid; u < 1152; u += 512)
        idxs[u] = g_idx[((size_t)b * HW + t0) * 9 + u];

    int og = tid & 15;
    int tg = tid >> 4;
    float4 acc0 = make_float4(0.f,0.f,0.f,0.f);
    float4 acc1 = make_float4(0.f,0.f,0.f,0.f);
    float4 acc2 = make_float4(0.f,0.f,0.f,0.f);
    float4 acc3 = make_float4(0.f,0.f,0.f,0.f);

    const float4* xT4 = ((const float4*)g_xT) + (size_t)b * HW * 16;
    const float4* W4  = (const float4*)Wsm;
    float4* g4 = (float4*)gbuf;                // row stride 17 float4
    const float* gp0 = gbuf + (tg * 4 + 0) * 68;
    const float* gp1 = gbuf + (tg * 4 + 1) * 68;
    const float* gp2 = gbuf + (tg * 4 + 2) * 68;
    const float* gp3 = gbuf + (tg * 4 + 3) * 68;
    int c4  = tid & 15;                        // per-thread gather coords
    int tl0 = tid >> 4;                        // rows tl0, +32, +64, +96
    __syncthreads();                           // idxs ready

    float4 r0 = __ldcg(&xT4[idxs[(tl0     ) * 9] * 16 + c4]);
    float4 r1 = __ldcg(&xT4[idxs[(tl0 + 32) * 9] * 16 + c4]);
    float4 r2 = __ldcg(&xT4[idxs[(tl0 + 64) * 9] * 16 + c4]);
    float4 r3 = __ldcg(&xT4[idxs[(tl0 + 96) * 9] * 16 + c4]);

    for (int kk = 0; kk < 9; ++kk) {
        g4[(tl0     ) * 17 + c4] = r0;
        g4[(tl0 + 32) * 17 + c4] = r1;
        g4[(tl0 + 64) * 17 + c4] = r2;
        g4[(tl0 + 96) * 17 + c4] = r3;
        __syncthreads();                       // gbuf ready
        if (kk < 8) {                          // prefetch next, hidden by compute
            r0 = __ldcg(&xT4[idxs[(tl0     ) * 9 + kk + 1] * 16 + c4]);
            r1 = __ldcg(&xT4[idxs[(tl0 + 32) * 9 + kk + 1] * 16 + c4]);
            r2 = __ldcg(&xT4[idxs[(tl0 + 64) * 9 + kk + 1] * 16 + c4]);
            r3 = __ldcg(&xT4[idxs[(tl0 + 96) * 9 + kk + 1] * 16 + c4]);
        }
        int rg0 = kk << 6;
        #pragma unroll 4
        for (int rl = 0; rl < 64; ++rl) {
            float4 wv = W4[((rg0 + rl) << 4) + og];
            float gA = gp0[rl];
            float gB = gp1[rl];
            float gC = gp2[rl];
            float gD = gp3[rl];
            acc0.x = fmaf(wv.x, gA, acc0.x); acc0.y = fmaf(wv.y, gA, acc0.y);
            acc0.z = fmaf(wv.z, gA, acc0.z); acc0.w = fmaf(wv.w, gA, acc0.w);
            acc1.x = fmaf(wv.x, gB, acc1.x); acc1.y = fmaf(wv.y, gB, acc1.y);
            acc1.z = fmaf(wv.z, gB, acc1.z); acc1.w = fmaf(wv.w, gB, acc1.w);
            acc2.x = fmaf(wv.x, gC, acc2.x); acc2.y = fmaf(wv.y, gC, acc2.y);
            acc2.z = fmaf(wv.z, gC, acc2.z); acc2.w = fmaf(wv.w, gC, acc2.w);
            acc3.x = fmaf(wv.x, gD, acc3.x); acc3.y = fmaf(wv.y, gD, acc3.y);
            acc3.z = fmaf(wv.z, gD, acc3.z); acc3.w = fmaf(wv.w, gD, acc3.w);
        }
        __syncthreads();                       // compute done before next store
    }

    float gamma0 = __ldg(gamma);
    float4 bv = __ldg(((const float4*)bias) + og);
    int o0 = og << 2;
    float4 accs[4] = {acc0, acc1, acc2, acc3};
    #pragma unroll
    for (int j = 0; j < 4; ++j) {
        int t = t0 + tg * 4 + j;
        float4 res = __ldcg(&((const float4*)g_xT)[((size_t)b * HW + t) * 16 + og]);
        float* outp = out + ((size_t)b * 64 + o0) * HW + t;
        outp[0]      = fmaf(gamma0, fmaxf(accs[j].x + bv.x, 0.f), res.x);
        outp[HW]     = fmaf(gamma0, fmaxf(accs[j].y + bv.y, 0.f), res.y);
        outp[2 * HW] = fmaf(gamma0, fmaxf(accs[j].z + bv.z, 0.f), res.z);
        outp[3 * HW] = fmaf(gamma0, fmaxf(accs[j].w + bv.w, 0.f), res.w);
    }
}

// ---------------- launch ----------------------------------------------------
extern "C" void kernel_launch(void* const* d_in, const int* in_sizes, int n_in,
                              void* d_out, int out_size) {
    const float* x      = (const float*)d_in[0];
    const float* qw     = (const float*)d_in[1];
    const float* qb     = (const float*)d_in[2];
    const float* kw     = (const float*)d_in[3];
    const float* kb     = (const float*)d_in[4];
    const float* gamma  = (const float*)d_in[5];
    const float* weight = (const float*)d_in[6];
    const float* bias   = (const float*)d_in[7];
    float* out = (float*)d_out;

    // k_topk2: (4096 + 16*516)*4 = 49408 B ; k_conv: (36864+8704)*4+4608 = 186880 B
    cudaFuncSetAttribute(k_topk2, cudaFuncAttributeMaxDynamicSharedMemorySize, 49408);
    cudaFuncSetAttribute(k_conv,  cudaFuncAttributeMaxDynamicSharedMemorySize, 186880);

    k_prep_w<<<144, 256>>>(weight);
    k_proj<<<128, 128>>>(x, qw, qb, kw, kb);
    k_topk2<<<1024, 512, 49408>>>();
    k_conv<<<128, 512, 186880>>>(bias, gamma, out);
}